// round 1
// baseline (speedup 1.0000x reference)
#include <cuda_runtime.h>
#include <math.h>

// Problem constants
#define NPOS   3
#define BSZ    2048
#define DN     128
#define NN     8192            // (1+NPOS)*B
#define XROWS  (NPOS*BSZ)      // 6144
#define INV_TEMP 10.0f

// GEMM tile config
#define BM 128
#define BN 64
#define CS 2048                // columns per block (col-split 4)
#define SA_STRIDE 129          // As[m][k] pad -> conflict-free scalar a-reads
#define SB_STRIDE 68           // Bs[k][n] pad -> aligned float4 b-reads

// Scratch (device globals: no allocation allowed)
__device__ float g_zn[NN * DN];     // normalized rows   [N][D]
__device__ float g_znT[DN * NN];    // transposed copy   [D][N]
__device__ float g_sumexp[NN];
__device__ float g_pos;

// ---------------------------------------------------------------------------
// Kernel 1: normalize rows of z = cat(x, x_pair); write zn and znT; zero accums
// 1 warp per row; grid 1024 x 256
// ---------------------------------------------------------------------------
__global__ void knorm(const float* __restrict__ x, const float* __restrict__ xp)
{
    int gid  = blockIdx.x * blockDim.x + threadIdx.x;
    if (gid < NN) g_sumexp[gid] = 0.0f;
    if (gid == 0) g_pos = 0.0f;

    int row  = gid >> 5;
    int lane = gid & 31;

    const float* src = (row < XROWS) ? (x + (size_t)row * DN)
                                     : (xp + (size_t)(row - XROWS) * DN);
    float4 v = ((const float4*)src)[lane];
    float ss = v.x * v.x + v.y * v.y + v.z * v.z + v.w * v.w;
#pragma unroll
    for (int o = 16; o; o >>= 1) ss += __shfl_xor_sync(0xffffffffu, ss, o);
    float r = rsqrtf(ss);
    float4 o4 = make_float4(v.x * r, v.y * r, v.z * r, v.w * r);

    ((float4*)g_zn)[row * 32 + lane] = o4;

    int k0 = lane * 4;
    g_znT[(k0 + 0) * NN + row] = o4.x;
    g_znT[(k0 + 1) * NN + row] = o4.y;
    g_znT[(k0 + 2) * NN + row] = o4.z;
    g_znT[(k0 + 3) * NN + row] = o4.w;
}

// ---------------------------------------------------------------------------
// Kernel 2: positive term  g_pos = sum_{p,b} dot(zn[p*B+b], zn[XROWS+b])
// 1 warp per b; grid 256 x 256
// ---------------------------------------------------------------------------
__global__ void kpos()
{
    int warp = threadIdx.x >> 5;
    int lane = threadIdx.x & 31;
    int b    = blockIdx.x * 8 + warp;

    const float4* Z = (const float4*)g_zn;
    float4 p = Z[(XROWS + b) * 32 + lane];
    float acc = 0.0f;
#pragma unroll
    for (int q = 0; q < NPOS; q++) {
        float4 a = Z[(q * BSZ + b) * 32 + lane];
        acc += a.x * p.x + a.y * p.y + a.z * p.z + a.w * p.w;
    }
#pragma unroll
    for (int o = 16; o; o >>= 1) acc += __shfl_xor_sync(0xffffffffu, acc, o);

    __shared__ float wsum[8];
    if (lane == 0) wsum[warp] = acc;
    __syncthreads();
    if (threadIdx.x == 0) {
        float s = 0.0f;
#pragma unroll
        for (int i = 0; i < 8; i++) s += wsum[i];
        atomicAdd(&g_pos, s);
    }
}

// ---------------------------------------------------------------------------
// Kernel 3: fused GEMM + exp row-accumulate.
// Block: 256 threads (tx 0..15, ty 0..15), microtile 8x4.
// grid = (4 col-chunks, 64 row-tiles). Dynamic smem ~101KB -> 2 blocks/SM.
// ---------------------------------------------------------------------------
__global__ void __launch_bounds__(256, 2) kmain()
{
    extern __shared__ float sm[];
    float* As = sm;                        // [BM][SA_STRIDE]  zn rows, natural
    float* Bs = sm + BM * SA_STRIDE;       // [DN][SB_STRIDE]  znT rows

    int tid = threadIdx.x;
    int tx  = tid & 15;
    int ty  = tid >> 4;
    int rm0   = blockIdx.y * BM;
    int cbase = blockIdx.x * CS;

    // Load full A tile once: 128 rows x 128 k (64KB). Coalesced; conflict-free STS.
    const float4* Z4 = (const float4*)g_zn;
#pragma unroll
    for (int it = 0; it < 16; ++it) {
        int idx = it * 256 + tid;
        int m   = idx >> 5;       // constant per warp
        int c   = idx & 31;       // = lane
        float4 v = Z4[(rm0 + m) * 32 + c];
        float* dst = As + m * SA_STRIDE + c * 4;
        dst[0] = v.x; dst[1] = v.y; dst[2] = v.z; dst[3] = v.w;
    }

    float rowsum[8];
#pragma unroll
    for (int i = 0; i < 8; i++) rowsum[i] = 0.0f;

    for (int t = 0; t < CS / BN; ++t) {    // 32 column tiles of 64
        int cn0 = cbase + t * BN;
        __syncthreads();                   // protect Bs before overwrite
        // Load B tile from pre-transposed znT: Bs[k][n] = zn[cn0+n][k]
#pragma unroll
        for (int it = 0; it < 8; ++it) {
            int idx = it * 256 + tid;
            int k   = idx >> 4;
            int n4  = idx & 15;
            float4 v = ((const float4*)(g_znT + (size_t)k * NN + cn0))[n4];
            *((float4*)(Bs + k * SB_STRIDE + n4 * 4)) = v;
        }
        __syncthreads();

        float acc[8][4];
#pragma unroll
        for (int i = 0; i < 8; i++)
#pragma unroll
            for (int j = 0; j < 4; j++) acc[i][j] = 0.0f;

        const float* arow = As + (ty * 8) * SA_STRIDE;
        const float* bcol = Bs + tx * 4;
#pragma unroll 8
        for (int k = 0; k < DN; k++) {
            float4 b = *((const float4*)(bcol + k * SB_STRIDE));
            float a0 = arow[0 * SA_STRIDE + k];
            float a1 = arow[1 * SA_STRIDE + k];
            float a2 = arow[2 * SA_STRIDE + k];
            float a3 = arow[3 * SA_STRIDE + k];
            float a4 = arow[4 * SA_STRIDE + k];
            float a5 = arow[5 * SA_STRIDE + k];
            float a6 = arow[6 * SA_STRIDE + k];
            float a7 = arow[7 * SA_STRIDE + k];
            acc[0][0] += a0 * b.x; acc[0][1] += a0 * b.y; acc[0][2] += a0 * b.z; acc[0][3] += a0 * b.w;
            acc[1][0] += a1 * b.x; acc[1][1] += a1 * b.y; acc[1][2] += a1 * b.z; acc[1][3] += a1 * b.w;
            acc[2][0] += a2 * b.x; acc[2][1] += a2 * b.y; acc[2][2] += a2 * b.z; acc[2][3] += a2 * b.w;
            acc[3][0] += a3 * b.x; acc[3][1] += a3 * b.y; acc[3][2] += a3 * b.z; acc[3][3] += a3 * b.w;
            acc[4][0] += a4 * b.x; acc[4][1] += a4 * b.y; acc[4][2] += a4 * b.z; acc[4][3] += a4 * b.w;
            acc[5][0] += a5 * b.x; acc[5][1] += a5 * b.y; acc[5][2] += a5 * b.z; acc[5][3] += a5 * b.w;
            acc[6][0] += a6 * b.x; acc[6][1] += a6 * b.y; acc[6][2] += a6 * b.z; acc[6][3] += a6 * b.w;
            acc[7][0] += a7 * b.x; acc[7][1] += a7 * b.y; acc[7][2] += a7 * b.z; acc[7][3] += a7 * b.w;
        }

        // exp + accumulate, skipping the diagonal element
#pragma unroll
        for (int i = 0; i < 8; i++) {
            int rg = rm0 + ty * 8 + i;
            float s = 0.0f;
#pragma unroll
            for (int j = 0; j < 4; j++) {
                int cg = cn0 + tx * 4 + j;
                float e = __expf(acc[i][j] * INV_TEMP);
                s += (rg == cg) ? 0.0f : e;
            }
            rowsum[i] += s;
        }
    }

    // Reduce over tx (lane = (ty&1)*16 + tx; xor<=8 stays within the tx group)
#pragma unroll
    for (int i = 0; i < 8; i++) {
        float s = rowsum[i];
#pragma unroll
        for (int o = 8; o; o >>= 1) s += __shfl_xor_sync(0xffffffffu, s, o);
        if (tx == 0) atomicAdd(&g_sumexp[rm0 + ty * 8 + i], s);
    }
}

// ---------------------------------------------------------------------------
// Kernel 4: final reduction -> scalar loss
// loss_neg = mean_i log(sumexp_i) + log(N_NEG/(N-1));  loss = loss_neg - loss_pos
// ---------------------------------------------------------------------------
__global__ void kfinal(float* __restrict__ out)
{
    __shared__ float red[256];
    int tid = threadIdx.x;
    float s = 0.0f;
    for (int i = tid; i < NN; i += 256) s += logf(g_sumexp[i]);
    red[tid] = s;
    __syncthreads();
    for (int o = 128; o; o >>= 1) {
        if (tid < o) red[tid] += red[tid + o];
        __syncthreads();
    }
    if (tid == 0) {
        float loss_neg = red[0] / (float)NN + logf(4096.0f / (float)(NN - 1));
        float loss_pos = g_pos * INV_TEMP / (float)XROWS;  // WEIGHT=1, /(NPOS*B)
        out[0] = loss_neg - loss_pos;
    }
}

// ---------------------------------------------------------------------------
extern "C" void kernel_launch(void* const* d_in, const int* in_sizes, int n_in,
                              void* d_out, int out_size)
{
    const float* x  = (const float*)d_in[0];
    const float* xp = (const float*)d_in[1];
    if (n_in >= 2 && in_sizes[0] == BSZ * DN) {  // robust to input ordering
        x  = (const float*)d_in[1];
        xp = (const float*)d_in[0];
    }

    size_t smem = (size_t)(BM * SA_STRIDE + DN * SB_STRIDE) * sizeof(float); // ~101KB
    cudaFuncSetAttribute(kmain, cudaFuncAttributeMaxDynamicSharedMemorySize, (int)smem);

    knorm<<<(NN * 32) / 256, 256>>>(x, xp);
    kpos<<<BSZ / 8, 256>>>();
    dim3 grid(NN / CS, NN / BM);   // (4, 64)
    kmain<<<grid, 256, smem>>>();
    kfinal<<<1, 256>>>((float*)d_out);
}

// round 3
// speedup vs baseline: 6.2299x; 6.2299x over previous
#include <cuda_runtime.h>
#include <cuda_bf16.h>
#include <math.h>
#include <stdint.h>

// Problem constants
#define NPOS   3
#define BSZ    2048
#define DN     128
#define NN     8192
#define XROWS  (NPOS*BSZ)
#define INV_TEMP 10.0f
#define LOG2E10  14.426950408889634f   // 10 / ln(2)

#define NTILES 8                       // 128-wide column tiles per CTA strip
#define SMEM_BYTES 98304               // A 32KB + B 2x32KB

// Scratch (device globals — no allocation allowed)
__device__ __nv_bfloat16 g_bA[NN * DN];   // unit rows * (10/ln2)
__device__ __nv_bfloat16 g_bB[NN * DN];   // unit rows
__device__ float g_sumexp[NN];
__device__ float g_pos;

// ---------------------------------------------------------------- helpers
__device__ __forceinline__ uint32_t s2u(const void* p) {
    uint32_t a;
    asm("{ .reg .u64 t; cvta.to.shared.u64 t, %1; cvt.u32.u64 %0, t; }" : "=r"(a) : "l"(p));
    return a;
}
__device__ __forceinline__ float ex2(float x) {
    float y; asm("ex2.approx.ftz.f32 %0, %1;" : "=f"(y) : "f"(x)); return y;
}
__device__ __forceinline__ float lg2(float x) {
    float y; asm("lg2.approx.f32 %0, %1;" : "=f"(y) : "f"(x)); return y;
}
__device__ __forceinline__ void ldmx4(uint32_t& r0, uint32_t& r1, uint32_t& r2,
                                      uint32_t& r3, uint32_t a) {
    asm volatile("ldmatrix.sync.aligned.m8n8.x4.shared.b16 {%0,%1,%2,%3}, [%4];"
                 : "=r"(r0), "=r"(r1), "=r"(r2), "=r"(r3) : "r"(a));
}
__device__ __forceinline__ void mmabf16(float* d, uint32_t a0, uint32_t a1,
                                        uint32_t a2, uint32_t a3,
                                        uint32_t b0, uint32_t b1) {
    asm volatile(
        "mma.sync.aligned.m16n8k16.row.col.f32.bf16.bf16.f32 "
        "{%0,%1,%2,%3},{%4,%5,%6,%7},{%8,%9},{%0,%1,%2,%3};"
        : "+f"(d[0]), "+f"(d[1]), "+f"(d[2]), "+f"(d[3])
        : "r"(a0), "r"(a1), "r"(a2), "r"(a3), "r"(b0), "r"(b1));
}

// Load one 128x128-bf16 tile into smem, XOR-swizzled: row*256B, 16B chunk
// c stored at (c ^ (row&7)). Conflict-free for ldmatrix column reads.
__device__ __forceinline__ void load_tile(uint32_t sdst, const __nv_bfloat16* src,
                                          int row0, int tid) {
#pragma unroll
    for (int i = 0; i < 8; i++) {
        int idx = i * 256 + tid;          // 2048 chunks of 16B
        int r = idx >> 4;
        int c = idx & 15;
        uint32_t off = (uint32_t)r * 256u + (uint32_t)((c ^ (r & 7)) << 4);
        const char* g = (const char*)(src + (size_t)(row0 + r) * DN) + (c << 4);
        asm volatile("cp.async.cg.shared.global [%0], [%1], 16;"
                     :: "r"(sdst + off), "l"(g));
    }
}

// ---------------------------------------------------------------------------
// Kernel 1: normalize rows, write bf16 operands; zero accumulators.
// ---------------------------------------------------------------------------
__global__ void knorm(const float* __restrict__ x, const float* __restrict__ xp)
{
    int gid  = blockIdx.x * blockDim.x + threadIdx.x;
    if (gid < NN) g_sumexp[gid] = 0.0f;
    if (gid == 0) g_pos = 0.0f;

    int row  = gid >> 5;
    int lane = gid & 31;

    const float* src = (row < XROWS) ? (x + (size_t)row * DN)
                                     : (xp + (size_t)(row - XROWS) * DN);
    float4 v = ((const float4*)src)[lane];
    float ss = v.x*v.x + v.y*v.y + v.z*v.z + v.w*v.w;
#pragma unroll
    for (int o = 16; o; o >>= 1) ss += __shfl_xor_sync(0xffffffffu, ss, o);
    float r = rsqrtf(ss);

    float bx = v.x * r, by = v.y * r, bz = v.z * r, bw = v.w * r;
    __nv_bfloat162* B2 = (__nv_bfloat162*)g_bB + (size_t)row * 64 + lane * 2;
    B2[0] = __floats2bfloat162_rn(bx, by);
    B2[1] = __floats2bfloat162_rn(bz, bw);

    float s = LOG2E10;
    __nv_bfloat162* A2 = (__nv_bfloat162*)g_bA + (size_t)row * 64 + lane * 2;
    A2[0] = __floats2bfloat162_rn(bx * s, by * s);
    A2[1] = __floats2bfloat162_rn(bz * s, bw * s);
}

// ---------------------------------------------------------------------------
// Kernel 2: positive term. 1 warp per b.
// ---------------------------------------------------------------------------
__global__ void kpos()
{
    int warp = threadIdx.x >> 5;
    int lane = threadIdx.x & 31;
    int b    = blockIdx.x * 8 + warp;

    const __nv_bfloat162* P = (const __nv_bfloat162*)g_bB + (size_t)(XROWS + b) * 64 + lane * 2;
    float2 p0 = __bfloat1622float2(P[0]);
    float2 p1 = __bfloat1622float2(P[1]);
    float acc = 0.0f;
#pragma unroll
    for (int q = 0; q < NPOS; q++) {
        const __nv_bfloat162* A = (const __nv_bfloat162*)g_bB + (size_t)(q * BSZ + b) * 64 + lane * 2;
        float2 a0 = __bfloat1622float2(A[0]);
        float2 a1 = __bfloat1622float2(A[1]);
        acc += a0.x*p0.x + a0.y*p0.y + a1.x*p1.x + a1.y*p1.y;
    }
#pragma unroll
    for (int o = 16; o; o >>= 1) acc += __shfl_xor_sync(0xffffffffu, acc, o);

    __shared__ float wsum[8];
    if (lane == 0) wsum[warp] = acc;
    __syncthreads();
    if (threadIdx.x == 0) {
        float s = 0.0f;
#pragma unroll
        for (int i = 0; i < 8; i++) s += wsum[i];
        atomicAdd(&g_pos, s);
    }
}

// ---------------------------------------------------------------------------
// Kernel 3: HMMA (mma.sync bf16) fused GEMM + exp row-accumulate.
// CTA: 128 rows x 1024 cols (8 tiles of 128x128). 256 threads = 8 warps,
// warp tile 64x32 (warps 2(m) x 4(n)). B double-buffered via cp.async.
// grid (8, 64).
// ---------------------------------------------------------------------------
__global__ void __launch_bounds__(256, 2) kmain()
{
    extern __shared__ char smc[];
    uint32_t sb = s2u(smc);
    uint32_t Ab = sb;
    uint32_t Bb = sb + 32768u;

    int tid  = threadIdx.x;
    int wid  = tid >> 5;
    int lane = tid & 31;
    int rm0   = blockIdx.y * 128;
    int cbase = blockIdx.x * (NTILES * 128);

    int wm = (wid & 1) * 64;     // warp m-offset within tile
    int wn = (wid >> 1) * 32;    // warp n-offset within tile

    // ldmatrix lane mapping: lanes 0-15 -> rows, lane>>4 -> k-chunk select
    int rr = lane & 15;
    int ch = lane >> 4;

    load_tile(Ab, g_bA, rm0, tid);
    load_tile(Bb, g_bB, cbase, tid);
    asm volatile("cp.async.commit_group;");

    // Precompute ldmatrix base offsets
    uint32_t aoff[4]; uint32_t a7[4];
#pragma unroll
    for (int mi = 0; mi < 4; mi++) {
        int row = wm + mi * 16 + rr;
        aoff[mi] = Ab + (uint32_t)row * 256u;
        a7[mi]   = (uint32_t)(row & 7);
    }
    uint32_t boff[2]; uint32_t b7[2];
#pragma unroll
    for (int np = 0; np < 2; np++) {
        int row = wn + np * 16 + rr;
        boff[np] = (uint32_t)row * 256u;
        b7[np]   = (uint32_t)(row & 7);
    }

    float rowsum[8];
#pragma unroll
    for (int i = 0; i < 8; i++) rowsum[i] = 0.0f;

    int tq = lane >> 2;          // D-fragment row-in-8
    int tc = (lane & 3) * 2;     // D-fragment col base

    for (int t = 0; t < NTILES; t++) {
        int buf = t & 1;
        __syncthreads();                       // all warps done with buf^1
        if (t + 1 < NTILES) {
            load_tile(Bb + (uint32_t)(buf ^ 1) * 32768u, g_bB,
                      cbase + (t + 1) * 128, tid);
            asm volatile("cp.async.commit_group;");
            asm volatile("cp.async.wait_group 1;" ::: "memory");
        } else {
            asm volatile("cp.async.wait_group 0;" ::: "memory");
        }
        __syncthreads();

        uint32_t Bbase = Bb + (uint32_t)buf * 32768u;

        float acc[4][4][4];
#pragma unroll
        for (int mi = 0; mi < 4; mi++)
#pragma unroll
            for (int ni = 0; ni < 4; ni++)
#pragma unroll
                for (int e = 0; e < 4; e++) acc[mi][ni][e] = 0.0f;

#pragma unroll
        for (int ks = 0; ks < 8; ks++) {
            uint32_t c0 = (uint32_t)(ks * 2 + ch);
            uint32_t b[2][4];
#pragma unroll
            for (int np = 0; np < 2; np++)
                ldmx4(b[np][0], b[np][1], b[np][2], b[np][3],
                      Bbase + boff[np] + ((c0 ^ b7[np]) << 4));
#pragma unroll
            for (int mi = 0; mi < 4; mi++) {
                uint32_t a0, a1, a2, a3;
                ldmx4(a0, a1, a2, a3, aoff[mi] + ((c0 ^ a7[mi]) << 4));
#pragma unroll
                for (int np = 0; np < 2; np++) {
                    mmabf16(acc[mi][np*2],     a0, a1, a2, a3, b[np][0], b[np][2]);
                    mmabf16(acc[mi][np*2 + 1], a0, a1, a2, a3, b[np][1], b[np][3]);
                }
            }
        }

        // epilogue: exp, skip diagonal, accumulate row sums
        int cn0 = cbase + t * 128;
        if (cn0 == rm0) {
#pragma unroll
            for (int mi = 0; mi < 4; mi++)
#pragma unroll
                for (int ni = 0; ni < 4; ni++)
#pragma unroll
                    for (int e = 0; e < 4; e++) {
                        int r = wm + mi * 16 + tq + (e >> 1) * 8;
                        int c = wn + ni * 8 + tc + (e & 1);
                        float v = ex2(acc[mi][ni][e]);
                        if (r == c) v = 0.0f;
                        rowsum[mi * 2 + (e >> 1)] += v;
                    }
        } else {
#pragma unroll
            for (int mi = 0; mi < 4; mi++)
#pragma unroll
                for (int ni = 0; ni < 4; ni++)
#pragma unroll
                    for (int e = 0; e < 4; e++) {
                        float v = ex2(acc[mi][ni][e]);
                        rowsum[mi * 2 + (e >> 1)] += v;
                    }
        }
    }

    // quad-reduce (lanes differing in bits 0-1 share the same rows)
#pragma unroll
    for (int i = 0; i < 8; i++) {
        float s = rowsum[i];
        s += __shfl_xor_sync(0xffffffffu, s, 1);
        s += __shfl_xor_sync(0xffffffffu, s, 2);
        rowsum[i] = s;
    }
    if ((lane & 3) == 0) {
#pragma unroll
        for (int mi = 0; mi < 4; mi++)
#pragma unroll
            for (int h = 0; h < 2; h++)
                atomicAdd(&g_sumexp[rm0 + wm + mi * 16 + h * 8 + tq],
                          rowsum[mi * 2 + h]);
    }
}

// ---------------------------------------------------------------------------
// Kernel 4: final reduction -> scalar loss
// ---------------------------------------------------------------------------
__global__ void kfinal(float* __restrict__ out)
{
    __shared__ float red[256];
    int tid = threadIdx.x;
    const float LN2 = 0.6931471805599453f;
    float s = 0.0f;
    for (int i = tid; i < NN; i += 256) s += lg2(g_sumexp[i]);
    red[tid] = s;
    __syncthreads();
    for (int o = 128; o; o >>= 1) {
        if (tid < o) red[tid] += red[tid + o];
        __syncthreads();
    }
    if (tid == 0) {
        float loss_neg = red[0] * LN2 / (float)NN + logf(4096.0f / (float)(NN - 1));
        float loss_pos = g_pos * INV_TEMP / (float)XROWS;
        out[0] = loss_neg - loss_pos;
    }
}

// ---------------------------------------------------------------------------
extern "C" void kernel_launch(void* const* d_in, const int* in_sizes, int n_in,
                              void* d_out, int out_size)
{
    const float* x  = (const float*)d_in[0];
    const float* xp = (const float*)d_in[1];
    if (n_in >= 2 && in_sizes[0] == BSZ * DN) {
        x  = (const float*)d_in[1];
        xp = (const float*)d_in[0];
    }

    cudaFuncSetAttribute(kmain, cudaFuncAttributeMaxDynamicSharedMemorySize, SMEM_BYTES);

    knorm<<<(NN * 32) / 256, 256>>>(x, xp);
    kpos<<<BSZ / 8, 256>>>();
    dim3 grid(NN / (NTILES * 128), NN / 128);   // (8, 64)
    kmain<<<grid, 256, SMEM_BYTES>>>();
    kfinal<<<1, 256>>>((float*)d_out);
}